// round 1
// baseline (speedup 1.0000x reference)
#include <cuda_runtime.h>
#include <math.h>

// Problem constants
#define Mq 1024
#define Nn 4096
#define Dd 128
#define Pp 3072
#define Hh 32
#define NKEYS 4096   // P + M

// -------- device scratch (no allocations allowed) --------
__device__ float g_QKV[(size_t)3 * Mq * Nn];            // raw Q,K,V [3][M][N]   48 MB
__device__ float g_Q[(size_t)Hh * Mq * Dd];             // normed Q  [H][M][D]   16 MB
__device__ float g_K[(size_t)Hh * NKEYS * Dd];          // concat K  [H][NK][D]  64 MB
__device__ float g_V[(size_t)Hh * NKEYS * Dd];          // concat V  [H][NK][D]  64 MB
__device__ float g_S[(size_t)Hh * Mq * NKEYS];          // scores    [H][M][NK] 536 MB

// -------- SGEMM: 128x128x8 tiles, 8x8 per thread, 256 threads --------
#define BM 128
#define BN 128
#define BK 8
#define TM 8
#define TN 8

// C = A * B (all row-major), batched over blockIdx.z via element strides.
__global__ __launch_bounds__(256) void sgemm_nn(
    int Kdim,
    const float* __restrict__ A, int lda, long long sA,
    const float* __restrict__ B, int ldb, long long sB,
    float* __restrict__ C, int ldc, long long sC)
{
    __shared__ __align__(16) float As[BK][BM];
    __shared__ __align__(16) float Bs[BK][BN];

    const int bz = blockIdx.z;
    A += (long long)bz * sA;
    B += (long long)bz * sB;
    C += (long long)bz * sC;

    const int bm = blockIdx.y * BM;
    const int bn = blockIdx.x * BN;
    const int tid = threadIdx.x;
    const int tx = tid & 15;        // 0..15
    const int ty = tid >> 4;        // 0..15

    const int a_row = tid >> 1;           // 0..127
    const int a_col = (tid & 1) * 4;      // 0 or 4
    const int b_row = tid >> 5;           // 0..7
    const int b_col = (tid & 31) * 4;     // 0..124

    float acc[TM][TN];
#pragma unroll
    for (int i = 0; i < TM; i++)
#pragma unroll
        for (int j = 0; j < TN; j++) acc[i][j] = 0.0f;

    for (int k0 = 0; k0 < Kdim; k0 += BK) {
        float4 av = *(const float4*)(A + (long long)(bm + a_row) * lda + k0 + a_col);
        As[a_col + 0][a_row] = av.x;
        As[a_col + 1][a_row] = av.y;
        As[a_col + 2][a_row] = av.z;
        As[a_col + 3][a_row] = av.w;
        float4 bv = *(const float4*)(B + (long long)(k0 + b_row) * ldb + bn + b_col);
        *(float4*)&Bs[b_row][b_col] = bv;
        __syncthreads();

#pragma unroll
        for (int kk = 0; kk < BK; kk++) {
            float ra[TM], rb[TN];
            *(float4*)&ra[0] = *(const float4*)&As[kk][ty * TM];
            *(float4*)&ra[4] = *(const float4*)&As[kk][ty * TM + 4];
            *(float4*)&rb[0] = *(const float4*)&Bs[kk][tx * TN];
            *(float4*)&rb[4] = *(const float4*)&Bs[kk][tx * TN + 4];
#pragma unroll
            for (int i = 0; i < TM; i++)
#pragma unroll
                for (int j = 0; j < TN; j++)
                    acc[i][j] += ra[i] * rb[j];
        }
        __syncthreads();
    }

#pragma unroll
    for (int i = 0; i < TM; i++) {
        const int row = bm + ty * TM + i;
#pragma unroll
        for (int j = 0; j < TN; j += 4) {
            *(float4*)(C + (long long)row * ldc + bn + tx * TN + j) =
                make_float4(acc[i][j], acc[i][j + 1], acc[i][j + 2], acc[i][j + 3]);
        }
    }
}

// C = A * B^T : A row-major [M,K], B row-major [Nrows,K]; batched via blockIdx.z.
__global__ __launch_bounds__(256) void sgemm_nt(
    int Kdim,
    const float* __restrict__ A, int lda, long long sA,
    const float* __restrict__ B, int ldb, long long sB,
    float* __restrict__ C, int ldc, long long sC)
{
    __shared__ __align__(16) float As[BK][BM];
    __shared__ __align__(16) float Bs[BK][BN];

    const int bz = blockIdx.z;
    A += (long long)bz * sA;
    B += (long long)bz * sB;
    C += (long long)bz * sC;

    const int bm = blockIdx.y * BM;
    const int bn = blockIdx.x * BN;
    const int tid = threadIdx.x;
    const int tx = tid & 15;
    const int ty = tid >> 4;

    const int a_row = tid >> 1;
    const int a_col = (tid & 1) * 4;

    float acc[TM][TN];
#pragma unroll
    for (int i = 0; i < TM; i++)
#pragma unroll
        for (int j = 0; j < TN; j++) acc[i][j] = 0.0f;

    for (int k0 = 0; k0 < Kdim; k0 += BK) {
        float4 av = *(const float4*)(A + (long long)(bm + a_row) * lda + k0 + a_col);
        As[a_col + 0][a_row] = av.x;
        As[a_col + 1][a_row] = av.y;
        As[a_col + 2][a_row] = av.z;
        As[a_col + 3][a_row] = av.w;
        // B^T tile: Bs[k][n] = B[bn+n][k0+k]
        float4 bv = *(const float4*)(B + (long long)(bn + a_row) * ldb + k0 + a_col);
        Bs[a_col + 0][a_row] = bv.x;
        Bs[a_col + 1][a_row] = bv.y;
        Bs[a_col + 2][a_row] = bv.z;
        Bs[a_col + 3][a_row] = bv.w;
        __syncthreads();

#pragma unroll
        for (int kk = 0; kk < BK; kk++) {
            float ra[TM], rb[TN];
            *(float4*)&ra[0] = *(const float4*)&As[kk][ty * TM];
            *(float4*)&ra[4] = *(const float4*)&As[kk][ty * TM + 4];
            *(float4*)&rb[0] = *(const float4*)&Bs[kk][tx * TN];
            *(float4*)&rb[4] = *(const float4*)&Bs[kk][tx * TN + 4];
#pragma unroll
            for (int i = 0; i < TM; i++)
#pragma unroll
                for (int j = 0; j < TN; j++)
                    acc[i][j] += ra[i] * rb[j];
        }
        __syncthreads();
    }

#pragma unroll
    for (int i = 0; i < TM; i++) {
        const int row = bm + ty * TM + i;
#pragma unroll
        for (int j = 0; j < TN; j += 4) {
            *(float4*)(C + (long long)row * ldc + bn + tx * TN + j) =
                make_float4(acc[i][j], acc[i][j + 1], acc[i][j + 2], acc[i][j + 3]);
        }
    }
}

// -------- RMSNorm (q,k) + pack to [H, seq, D]; v packed without norm --------
__global__ __launch_bounds__(128) void norm_pack_kernel()
{
    const int which = blockIdx.y;        // 0=q, 1=k, 2=v
    const int row = blockIdx.x;          // 0..H*M-1
    const int m = row >> 5;              // row / H
    const int h = row & 31;              // row % H
    const int d = threadIdx.x;

    const float* src = g_QKV + (size_t)which * Mq * Nn + (size_t)m * Nn + (size_t)h * Dd;
    float x = src[d];

    float s = x * x;
#pragma unroll
    for (int o = 16; o > 0; o >>= 1) s += __shfl_xor_sync(0xffffffffu, s, o);
    __shared__ float ws[4];
    if ((d & 31) == 0) ws[d >> 5] = s;
    __syncthreads();
    const float tot = ws[0] + ws[1] + ws[2] + ws[3];
    const float scale = rsqrtf(tot * (1.0f / (float)Dd));

    const float outv = (which < 2) ? x * scale : x;
    float* dst;
    if (which == 0)      dst = g_Q + ((size_t)h * Mq + m) * Dd;
    else if (which == 1) dst = g_K + ((size_t)h * NKEYS + Pp + m) * Dd;
    else                 dst = g_V + ((size_t)h * NKEYS + Pp + m) * Dd;
    dst[d] = outv;
}

// -------- copy KV cache into concat buffers --------
__global__ __launch_bounds__(256) void cache_copy_kernel(
    const float* __restrict__ cK, const float* __restrict__ cV)
{
    const size_t n4 = (size_t)Hh * Pp * Dd / 4;
    for (size_t i = (size_t)blockIdx.x * blockDim.x + threadIdx.x; i < n4;
         i += (size_t)gridDim.x * blockDim.x) {
        const size_t e = i * 4;
        const size_t h = e / ((size_t)Pp * Dd);
        const size_t r = e % ((size_t)Pp * Dd);
        *(float4*)(g_K + h * (size_t)NKEYS * Dd + r) = *(const float4*)(cK + e);
        *(float4*)(g_V + h * (size_t)NKEYS * Dd + r) = *(const float4*)(cV + e);
    }
}

// -------- row softmax over g_S, in place; one block per (h,m) row --------
__global__ __launch_bounds__(256) void softmax_kernel()
{
    float* p = g_S + (size_t)blockIdx.x * NKEYS;
    const int t = threadIdx.x;
    float v[NKEYS / 256];

    float mx = -3.4e38f;
#pragma unroll
    for (int i = 0; i < NKEYS / 256; i++) {
        v[i] = p[t + (i << 8)];
        mx = fmaxf(mx, v[i]);
    }
    __shared__ float red[8];
#pragma unroll
    for (int o = 16; o > 0; o >>= 1) mx = fmaxf(mx, __shfl_xor_sync(0xffffffffu, mx, o));
    if ((t & 31) == 0) red[t >> 5] = mx;
    __syncthreads();
#pragma unroll
    for (int i = 0; i < 8; i++) mx = fmaxf(mx, red[i]);
    __syncthreads();

    float sum = 0.0f;
#pragma unroll
    for (int i = 0; i < NKEYS / 256; i++) {
        v[i] = __expf(v[i] - mx);
        sum += v[i];
    }
#pragma unroll
    for (int o = 16; o > 0; o >>= 1) sum += __shfl_xor_sync(0xffffffffu, sum, o);
    if ((t & 31) == 0) red[t >> 5] = sum;
    __syncthreads();
    sum = red[0] + red[1] + red[2] + red[3] + red[4] + red[5] + red[6] + red[7];
    const float inv = 1.0f / sum;

#pragma unroll
    for (int i = 0; i < NKEYS / 256; i++) p[t + (i << 8)] = v[i] * inv;
}

// -------- host launcher --------
extern "C" void kernel_launch(void* const* d_in, const int* in_sizes, int n_in,
                              void* d_out, int out_size)
{
    const float* X  = (const float*)d_in[0];
    const float* Wq = (const float*)d_in[1];
    const float* Wk = (const float*)d_in[2];
    const float* Wv = (const float*)d_in[3];
    const float* cK = (const float*)d_in[4];
    const float* cV = (const float*)d_in[5];
    float* out = (float*)d_out;

    float *qkv, *gq, *gk, *gv, *gs;
    cudaGetSymbolAddress((void**)&qkv, g_QKV);
    cudaGetSymbolAddress((void**)&gq,  g_Q);
    cudaGetSymbolAddress((void**)&gk,  g_K);
    cudaGetSymbolAddress((void**)&gv,  g_V);
    cudaGetSymbolAddress((void**)&gs,  g_S);

    // 1) QKV projections: [M,N] x [N,N] -> raw q/k/v
    {
        dim3 grid(Nn / BN, Mq / BM, 1);
        sgemm_nn<<<grid, 256>>>(Nn, X, Nn, 0, Wq, Nn, 0, qkv + (size_t)0 * Mq * Nn, Nn, 0);
        sgemm_nn<<<grid, 256>>>(Nn, X, Nn, 0, Wk, Nn, 0, qkv + (size_t)1 * Mq * Nn, Nn, 0);
        sgemm_nn<<<grid, 256>>>(Nn, X, Nn, 0, Wv, Nn, 0, qkv + (size_t)2 * Mq * Nn, Nn, 0);
    }

    // 2) KV cache concat copy (independent of 1)
    cache_copy_kernel<<<2048, 256>>>(cK, cV);

    // 3) RMSNorm q,k + pack all three to [H, seq, D]
    norm_pack_kernel<<<dim3(Hh * Mq, 3, 1), 128>>>();

    // 4) scores S[h] = Qn[h] (MxD) @ Kc[h]^T  -> [M, NKEYS] per head
    {
        dim3 grid(NKEYS / BN, Mq / BM, Hh);
        sgemm_nt<<<grid, 256>>>(Dd,
                                gq, Dd, (long long)Mq * Dd,
                                gk, Dd, (long long)NKEYS * Dd,
                                gs, NKEYS, (long long)Mq * NKEYS);
    }

    // 5) row softmax in place
    softmax_kernel<<<Hh * Mq, 256>>>();

    // 6) out[h] = S[h] (MxNK) @ Vc[h] (NKxD), written to [M, N] at col h*D
    {
        dim3 grid(Dd / BN, Mq / BM, Hh);   // (1, 8, 32)
        sgemm_nn<<<grid, 256>>>(NKEYS,
                                gs, NKEYS, (long long)Mq * NKEYS,
                                gv, Dd, (long long)NKEYS * Dd,
                                out, Nn, (long long)Dd);
    }
}

// round 3
// speedup vs baseline: 2.7761x; 2.7761x over previous
#include <cuda_runtime.h>
#include <cuda_bf16.h>
#include <math.h>
#include <stdint.h>

#define Mq 1024
#define Nn 4096
#define Dd 128
#define Pp 3072
#define Hh 32
#define NKEYS 4096
typedef __nv_bfloat16 bf16;

// ---------------- scratch (static device globals; no allocs) ----------------
__device__ bf16 g_Xh[(size_t)Mq * Nn],       g_Xl[(size_t)Mq * Nn];
__device__ bf16 g_Wh[(size_t)3 * Nn * Nn],   g_Wl[(size_t)3 * Nn * Nn];      // W^T
__device__ bf16 g_Qh[(size_t)Hh * Mq * Dd],  g_Ql[(size_t)Hh * Mq * Dd];
__device__ bf16 g_Kh[(size_t)Hh * NKEYS * Dd], g_Kl[(size_t)Hh * NKEYS * Dd];
__device__ bf16 g_Vth[(size_t)Hh * Dd * NKEYS], g_Vtl[(size_t)Hh * Dd * NKEYS]; // V^T
__device__ bf16 g_Sh[(size_t)Hh * Mq * NKEYS], g_Sl[(size_t)Hh * Mq * NKEYS];   // exp scores
__device__ float g_part[(size_t)64 * Hh * Mq];   // per (ntile,warp-half) partial row sums
__device__ float g_inv[(size_t)Hh * Mq];

// ---------------- helpers ----------------
static __device__ __forceinline__ uint32_t smem_u32(const void* p) {
    uint32_t a;
    asm("{ .reg .u64 t; cvta.to.shared.u64 t, %1; cvt.u32.u64 %0, t; }" : "=r"(a) : "l"(p));
    return a;
}
static __device__ __forceinline__ void cp_async16(uint32_t dst, const void* src) {
    asm volatile("cp.async.cg.shared.global [%0], [%1], 16;" :: "r"(dst), "l"(src));
}
#define CP_COMMIT() asm volatile("cp.async.commit_group;" ::: "memory")
#define CP_WAIT(n)  asm volatile("cp.async.wait_group %0;" :: "n"(n) : "memory")

static __device__ __forceinline__ void ldsm_x4(uint32_t& r0, uint32_t& r1, uint32_t& r2, uint32_t& r3,
                                               uint32_t addr) {
    asm volatile("ldmatrix.sync.aligned.m8n8.x4.shared.b16 {%0,%1,%2,%3}, [%4];"
                 : "=r"(r0), "=r"(r1), "=r"(r2), "=r"(r3) : "r"(addr));
}
static __device__ __forceinline__ void mma_bf16(float* c, const uint32_t* a, const uint32_t* b) {
    asm volatile(
        "mma.sync.aligned.m16n8k16.row.col.f32.bf16.bf16.f32 "
        "{%0,%1,%2,%3}, {%4,%5,%6,%7}, {%8,%9}, {%0,%1,%2,%3};"
        : "+f"(c[0]), "+f"(c[1]), "+f"(c[2]), "+f"(c[3])
        : "r"(a[0]), "r"(a[1]), "r"(a[2]), "r"(a[3]), "r"(b[0]), "r"(b[1]));
}
static __device__ __forceinline__ void split_bf16(float v, bf16& h, bf16& l) {
    h = __float2bfloat16(v);
    l = __float2bfloat16(v - __bfloat162float(h));
}

// smem: [0,1024) reduction buffer, then 2 stages * 4 planes * 16KB
#define SMEM_BYTES (1024 + 2 * 4 * 16384)

// ---------------- generic bf16x2-split NT GEMM (HMMA) ----------------
// C[m][n] = sum_k A[m][k]*B[n][k] with A,B each split hi/lo; 128x128 tile.
// MODE: 0 proj-Q (RMS->g_Q*), 1 proj-K (RMS->g_K*+P), 2 proj-V (transpose->g_Vt*),
//       3 scores (exp->g_S*,+partials), 4 PV (scale by g_inv -> outp fp32)
template <int MODE>
__global__ __launch_bounds__(256, 1) void mma_kernel(
    const bf16* __restrict__ Ah, const bf16* __restrict__ Al, int lda, long long sA,
    const bf16* __restrict__ Bh, const bf16* __restrict__ Bl, int ldb, long long sB,
    int kdim, float* __restrict__ outp)
{
    extern __shared__ char smem[];
    float* rbuf = (float*)smem;
    const uint32_t sb = smem_u32(smem);
    const int tid = threadIdx.x;
    const int wid = tid >> 5, l = tid & 31;
    const int wm = wid >> 1, wn = wid & 1;        // warp grid 4(m) x 2(n)
    const int bn = blockIdx.x * 128, bm = blockIdx.y * 128, z = blockIdx.z;

    const bf16* P0 = Ah + (size_t)z * sA;
    const bf16* P1 = Al + (size_t)z * sA;
    const bf16* P2 = Bh + (size_t)z * sB;
    const bf16* P3 = Bl + (size_t)z * sB;

    float acc[2][8][4];
#pragma unroll
    for (int t = 0; t < 2; t++)
#pragma unroll
        for (int nb = 0; nb < 8; nb++)
#pragma unroll
            for (int i = 0; i < 4; i++) acc[t][nb][i] = 0.f;

    const int nch = kdim >> 6;

    auto load_chunk = [&](int c) {
        const int st = c & 1;
        const int k0 = c << 6;
#pragma unroll
        for (int p = 0; p < 4; p++) {
            const bf16* src = (p == 0) ? P0 : (p == 1) ? P1 : (p == 2) ? P2 : P3;
            const int ld = (p < 2) ? lda : ldb;
            const int r0 = (p < 2) ? bm : bn;
            const uint32_t dstb = sb + 1024 + st * 65536 + p * 16384;
#pragma unroll
            for (int i = tid; i < 1024; i += 256) {
                const int row = i >> 3, cc = i & 7;
                const uint32_t off = (uint32_t)(row * 128 + cc * 16);
                cp_async16(dstb + (off ^ (uint32_t)((row & 7) << 4)),
                           src + (size_t)(r0 + row) * ld + k0 + cc * 8);
            }
        }
        CP_COMMIT();
    };

    load_chunk(0);
    if (nch > 1) load_chunk(1);

    for (int c = 0; c < nch; c++) {
        if (c + 1 < nch) { CP_WAIT(1); } else { CP_WAIT(0); }
        __syncthreads();
        const uint32_t sbase = sb + 1024 + (c & 1) * 65536;

#pragma unroll
        for (int pass = 0; pass < 3; pass++) {
            const int pa = (pass == 2) ? 1 : 0;
            const int pb = (pass == 1) ? 3 : 2;
            const uint32_t ab = sbase + pa * 16384;
            const uint32_t bb = sbase + pb * 16384;
#pragma unroll
            for (int kk = 0; kk < 4; kk++) {
                uint32_t a[2][4];
#pragma unroll
                for (int t = 0; t < 2; t++) {
                    const int mrow = wm * 32 + t * 16 + (l & 7) + ((l >> 3) & 1) * 8;
                    const int kb = kk * 32 + ((l >> 4) & 1) * 16;
                    ldsm_x4(a[t][0], a[t][1], a[t][2], a[t][3],
                            ab + (uint32_t)(mrow * 128) + (uint32_t)(kb ^ ((mrow & 7) << 4)));
                }
                uint32_t b[8][2];
#pragma unroll
                for (int bt = 0; bt < 4; bt++) {
                    const int nrow = wn * 64 + bt * 16 + (l & 7) + ((l >> 4) & 1) * 8;
                    const int kb = kk * 32 + ((l >> 3) & 1) * 16;
                    ldsm_x4(b[2 * bt][0], b[2 * bt][1], b[2 * bt + 1][0], b[2 * bt + 1][1],
                            bb + (uint32_t)(nrow * 128) + (uint32_t)(kb ^ ((nrow & 7) << 4)));
                }
#pragma unroll
                for (int t = 0; t < 2; t++)
#pragma unroll
                    for (int nb = 0; nb < 8; nb++)
                        mma_bf16(acc[t][nb], a[t], b[nb]);
            }
        }
        __syncthreads();
        if (c + 2 < nch) load_chunk(c + 2);
    }

    // ---------------- epilogues ----------------
    // accumulator mapping: value acc[t][nb][i]:
    //   row = wm*32 + t*16 + (l>>2) + (i>>1)*8
    //   col = wn*64 + nb*8 + (l&3)*2 + (i&1)

    if (MODE == 0 || MODE == 1) {
        // full-row (128-col) sumsq across the two n-warps via smem
        float ss[4] = {0.f, 0.f, 0.f, 0.f};   // slot s = t*2 + (i>>1)
#pragma unroll
        for (int t = 0; t < 2; t++)
#pragma unroll
            for (int nb = 0; nb < 8; nb++)
#pragma unroll
                for (int i = 0; i < 4; i++) {
                    const float v = acc[t][nb][i];
                    ss[t * 2 + (i >> 1)] += v * v;
                }
#pragma unroll
        for (int s = 0; s < 4; s++) {
            ss[s] += __shfl_xor_sync(0xffffffffu, ss[s], 1);
            ss[s] += __shfl_xor_sync(0xffffffffu, ss[s], 2);
        }
        if ((l & 3) == 0) {
#pragma unroll
            for (int s = 0; s < 4; s++) {
                const int row = wm * 32 + (s >> 1) * 16 + (l >> 2) + (s & 1) * 8;
                rbuf[wn * 128 + row] = ss[s];
            }
        }
        __syncthreads();

        bf16* dh = (MODE == 0) ? g_Qh : g_Kh;
        bf16* dl = (MODE == 0) ? g_Ql : g_Kl;
#pragma unroll
        for (int t = 0; t < 2; t++)
#pragma unroll
            for (int rh = 0; rh < 2; rh++) {
                const int row = wm * 32 + t * 16 + (l >> 2) + rh * 8;
                const float sc = rsqrtf((rbuf[row] + rbuf[128 + row]) * (1.0f / 128.0f));
                const size_t rowbase = (MODE == 0)
                    ? ((size_t)blockIdx.x * Mq + bm + row) * 128
                    : ((size_t)blockIdx.x * NKEYS + Pp + bm + row) * 128;
#pragma unroll
                for (int nb = 0; nb < 8; nb++) {
                    const int col = wn * 64 + nb * 8 + (l & 3) * 2;
                    const float v0 = acc[t][nb][rh * 2 + 0] * sc;
                    const float v1 = acc[t][nb][rh * 2 + 1] * sc;
                    bf16 h0, l0, h1, l1;
                    split_bf16(v0, h0, l0);
                    split_bf16(v1, h1, l1);
                    __nv_bfloat162 ph; ph.x = h0; ph.y = h1;
                    __nv_bfloat162 pl; pl.x = l0; pl.y = l1;
                    *(__nv_bfloat162*)(dh + rowbase + col) = ph;
                    *(__nv_bfloat162*)(dl + rowbase + col) = pl;
                }
            }
    } else if (MODE == 2) {
        // transposed store: row = seq, col = d; dst [head][d][P+seq]
        const int head = blockIdx.x;
#pragma unroll
        for (int t = 0; t < 2; t++)
#pragma unroll
            for (int nb = 0; nb < 8; nb++)
#pragma unroll
                for (int i = 0; i < 4; i++) {
                    const int row = t * 16 + (l >> 2) + (i >> 1) * 8 + wm * 32;
                    const int col = wn * 64 + nb * 8 + (l & 3) * 2 + (i & 1);
                    bf16 h, lo;
                    split_bf16(acc[t][nb][i], h, lo);
                    const size_t idx = ((size_t)head * Dd + col) * NKEYS + Pp + bm + row;
                    g_Vth[idx] = h;
                    g_Vtl[idx] = lo;
                }
    } else if (MODE == 3) {
        float rs[4] = {0.f, 0.f, 0.f, 0.f};
#pragma unroll
        for (int t = 0; t < 2; t++)
#pragma unroll
            for (int rh = 0; rh < 2; rh++) {
                const int row = wm * 32 + t * 16 + (l >> 2) + rh * 8;
                const size_t rowb = ((size_t)z * Mq + bm + row) * (size_t)NKEYS + bn;
#pragma unroll
                for (int nb = 0; nb < 8; nb++) {
                    const int col = wn * 64 + nb * 8 + (l & 3) * 2;
                    const float e0 = __expf(acc[t][nb][rh * 2 + 0]);
                    const float e1 = __expf(acc[t][nb][rh * 2 + 1]);
                    rs[t * 2 + rh] += e0 + e1;
                    bf16 h0, l0, h1, l1;
                    split_bf16(e0, h0, l0);
                    split_bf16(e1, h1, l1);
                    __nv_bfloat162 ph; ph.x = h0; ph.y = h1;
                    __nv_bfloat162 pl; pl.x = l0; pl.y = l1;
                    *(__nv_bfloat162*)(g_Sh + rowb + col) = ph;
                    *(__nv_bfloat162*)(g_Sl + rowb + col) = pl;
                }
            }
#pragma unroll
        for (int s = 0; s < 4; s++) {
            rs[s] += __shfl_xor_sync(0xffffffffu, rs[s], 1);
            rs[s] += __shfl_xor_sync(0xffffffffu, rs[s], 2);
        }
        if ((l & 3) == 0) {
            const size_t pb = (size_t)(blockIdx.x * 2 + wn) * (Hh * Mq) + (size_t)z * Mq + bm;
#pragma unroll
            for (int s = 0; s < 4; s++) {
                const int row = wm * 32 + (s >> 1) * 16 + (l >> 2) + (s & 1) * 8;
                g_part[pb + row] = rs[s];
            }
        }
    } else { // MODE 4
#pragma unroll
        for (int t = 0; t < 2; t++)
#pragma unroll
            for (int rh = 0; rh < 2; rh++) {
                const int row = wm * 32 + t * 16 + (l >> 2) + rh * 8;
                const float inv = g_inv[(size_t)z * Mq + bm + row];
                float* orow = outp + (size_t)(bm + row) * Nn + (size_t)z * Dd;
#pragma unroll
                for (int nb = 0; nb < 8; nb++) {
                    const int col = wn * 64 + nb * 8 + (l & 3) * 2;
                    float2 v;
                    v.x = acc[t][nb][rh * 2 + 0] * inv;
                    v.y = acc[t][nb][rh * 2 + 1] * inv;
                    *(float2*)(orow + col) = v;
                }
            }
    }
}

// ---------------- prep kernels ----------------
__global__ __launch_bounds__(256) void convert_X(const float* __restrict__ X) {
    const size_t n = (size_t)Mq * Nn;
    for (size_t i = (size_t)blockIdx.x * blockDim.x + threadIdx.x; i < n;
         i += (size_t)gridDim.x * blockDim.x) {
        bf16 h, lo;
        split_bf16(X[i], h, lo);
        g_Xh[i] = h;
        g_Xl[i] = lo;
    }
}

__global__ __launch_bounds__(256) void transpose_convert_W(
    const float* __restrict__ W, bf16* __restrict__ oh, bf16* __restrict__ ol)
{
    __shared__ float t[32][33];
    const int n0 = blockIdx.x * 32, k0 = blockIdx.y * 32;
    const int tx = threadIdx.x, ty = threadIdx.y;
#pragma unroll
    for (int j = 0; j < 4; j++)
        t[ty + 8 * j][tx] = W[(size_t)(k0 + ty + 8 * j) * Nn + n0 + tx];
    __syncthreads();
#pragma unroll
    for (int j = 0; j < 4; j++) {
        const float v = t[tx][ty + 8 * j];
        const size_t o = (size_t)(n0 + ty + 8 * j) * Nn + k0 + tx;
        bf16 h, lo;
        split_bf16(v, h, lo);
        oh[o] = h;
        ol[o] = lo;
    }
}

__global__ __launch_bounds__(256) void convert_cacheK(const float* __restrict__ cK) {
    const size_t n = (size_t)Hh * Pp * Dd;
    for (size_t i = (size_t)blockIdx.x * blockDim.x + threadIdx.x; i < n;
         i += (size_t)gridDim.x * blockDim.x) {
        const size_t h = i / ((size_t)Pp * Dd);
        const size_t rr = i % ((size_t)Pp * Dd);
        bf16 hh, lo;
        split_bf16(cK[i], hh, lo);
        const size_t o = h * (size_t)NKEYS * Dd + rr;
        g_Kh[o] = hh;
        g_Kl[o] = lo;
    }
}

__global__ __launch_bounds__(256) void transpose_convert_V(const float* __restrict__ cV) {
    __shared__ float t[32][33];
    const int h = blockIdx.z;
    const int p0 = blockIdx.x * 32, d0 = blockIdx.y * 32;
    const int tx = threadIdx.x, ty = threadIdx.y;
#pragma unroll
    for (int j = 0; j < 4; j++)
        t[ty + 8 * j][tx] = cV[((size_t)h * Pp + p0 + ty + 8 * j) * Dd + d0 + tx];
    __syncthreads();
#pragma unroll
    for (int j = 0; j < 4; j++) {
        const float v = t[tx][ty + 8 * j];
        const size_t o = ((size_t)h * Dd + d0 + ty + 8 * j) * NKEYS + p0 + tx;
        bf16 hh, lo;
        split_bf16(v, hh, lo);
        g_Vth[o] = hh;
        g_Vtl[o] = lo;
    }
}

__global__ __launch_bounds__(256) void reduce_inv() {
    const int r = blockIdx.x * blockDim.x + threadIdx.x;
    if (r < Hh * Mq) {
        float s = 0.f;
#pragma unroll
        for (int nt = 0; nt < 64; nt++) s += g_part[(size_t)nt * (Hh * Mq) + r];
        g_inv[r] = 1.0f / s;
    }
}

// ---------------- host launcher ----------------
extern "C" void kernel_launch(void* const* d_in, const int* in_sizes, int n_in,
                              void* d_out, int out_size)
{
    const float* X  = (const float*)d_in[0];
    const float* Wq = (const float*)d_in[1];
    const float* Wk = (const float*)d_in[2];
    const float* Wv = (const float*)d_in[3];
    const float* cK = (const float*)d_in[4];
    const float* cV = (const float*)d_in[5];
    float* out = (float*)d_out;

    bf16 *xh, *xl, *wh, *wl, *qh, *ql, *kh, *kl, *vth, *vtl, *sh, *sl;
    cudaGetSymbolAddress((void**)&xh, g_Xh);   cudaGetSymbolAddress((void**)&xl, g_Xl);
    cudaGetSymbolAddress((void**)&wh, g_Wh);   cudaGetSymbolAddress((void**)&wl, g_Wl);
    cudaGetSymbolAddress((void**)&qh, g_Qh);   cudaGetSymbolAddress((void**)&ql, g_Ql);
    cudaGetSymbolAddress((void**)&kh, g_Kh);   cudaGetSymbolAddress((void**)&kl, g_Kl);
    cudaGetSymbolAddress((void**)&vth, g_Vth); cudaGetSymbolAddress((void**)&vtl, g_Vtl);
    cudaGetSymbolAddress((void**)&sh, g_Sh);   cudaGetSymbolAddress((void**)&sl, g_Sl);

    cudaFuncSetAttribute(mma_kernel<0>, cudaFuncAttributeMaxDynamicSharedMemorySize, SMEM_BYTES);
    cudaFuncSetAttribute(mma_kernel<1>, cudaFuncAttributeMaxDynamicSharedMemorySize, SMEM_BYTES);
    cudaFuncSetAttribute(mma_kernel<2>, cudaFuncAttributeMaxDynamicSharedMemorySize, SMEM_BYTES);
    cudaFuncSetAttribute(mma_kernel<3>, cudaFuncAttributeMaxDynamicSharedMemorySize, SMEM_BYTES);
    cudaFuncSetAttribute(mma_kernel<4>, cudaFuncAttributeMaxDynamicSharedMemorySize, SMEM_BYTES);

    // prep
    convert_X<<<2048, 256>>>(X);
    transpose_convert_W<<<dim3(128, 128), dim3(32, 8)>>>(Wq, wh + (size_t)0 * Nn * Nn, wl + (size_t)0 * Nn * Nn);
    transpose_convert_W<<<dim3(128, 128), dim3(32, 8)>>>(Wk, wh + (size_t)1 * Nn * Nn, wl + (size_t)1 * Nn * Nn);
    transpose_convert_W<<<dim3(128, 128), dim3(32, 8)>>>(Wv, wh + (size_t)2 * Nn * Nn, wl + (size_t)2 * Nn * Nn);
    convert_cacheK<<<8192, 256>>>(cK);
    transpose_convert_V<<<dim3(Pp / 32, Dd / 32, Hh), dim3(32, 8)>>>(cV);

    // projections: A = X split, B = W^T split; n-tile == head
    {
        dim3 grid(Nn / 128, Mq / 128, 1);
        mma_kernel<0><<<grid, 256, SMEM_BYTES>>>(xh, xl, Nn, 0,
            wh + (size_t)0 * Nn * Nn, wl + (size_t)0 * Nn * Nn, Nn, 0, Nn, nullptr);
        mma_kernel<1><<<grid, 256, SMEM_BYTES>>>(xh, xl, Nn, 0,
            wh + (size_t)1 * Nn * Nn, wl + (size_t)1 * Nn * Nn, Nn, 0, Nn, nullptr);
        mma_kernel<2><<<grid, 256, SMEM_BYTES>>>(xh, xl, Nn, 0,
            wh + (size_t)2 * Nn * Nn, wl + (size_t)2 * Nn * Nn, Nn, 0, Nn, nullptr);
    }

    // scores: per head S = Qn @ Kc^T, epilogue exp + partial sums
    mma_kernel<3><<<dim3(NKEYS / 128, Mq / 128, Hh), 256, SMEM_BYTES>>>(
        qh, ql, Dd, (long long)Mq * Dd,
        kh, kl, Dd, (long long)NKEYS * Dd,
        Dd, nullptr);

    reduce_inv<<<(Hh * Mq) / 256, 256>>>();

    // PV: out = (expS @ V^T-rows) * inv_sum
    mma_kernel<4><<<dim3(1, Mq / 128, Hh), 256, SMEM_BYTES>>>(
        sh, sl, NKEYS, (long long)Mq * NKEYS,
        vth, vtl, NKEYS, (long long)Dd * NKEYS,
        NKEYS, out);
}

// round 4
// speedup vs baseline: 3.2922x; 1.1859x over previous
#include <cuda_runtime.h>
#include <cuda_bf16.h>
#include <math.h>
#include <stdint.h>

#define Mq 1024
#define Nn 4096
#define Dd 128
#define Pp 3072
#define Hh 32
#define NKEYS 4096
typedef __nv_bfloat16 bf16;

// ---------------- scratch ----------------
__device__ bf16 g_Xh[(size_t)Mq * Nn],       g_Xl[(size_t)Mq * Nn];
__device__ bf16 g_Wh[(size_t)3 * Nn * Nn],   g_Wl[(size_t)3 * Nn * Nn];      // W^T
__device__ bf16 g_Qh[(size_t)Hh * Mq * Dd],  g_Ql[(size_t)Hh * Mq * Dd];
__device__ bf16 g_Kh[(size_t)Hh * NKEYS * Dd], g_Kl[(size_t)Hh * NKEYS * Dd];
__device__ bf16 g_Vth[(size_t)Hh * Dd * NKEYS], g_Vtl[(size_t)Hh * Dd * NKEYS]; // V^T

// ---------------- helpers ----------------
static __device__ __forceinline__ uint32_t smem_u32(const void* p) {
    uint32_t a;
    asm("{ .reg .u64 t; cvta.to.shared.u64 t, %1; cvt.u32.u64 %0, t; }" : "=r"(a) : "l"(p));
    return a;
}
static __device__ __forceinline__ void cp_async16(uint32_t dst, const void* src) {
    asm volatile("cp.async.cg.shared.global [%0], [%1], 16;" :: "r"(dst), "l"(src));
}
#define CP_COMMIT() asm volatile("cp.async.commit_group;" ::: "memory")
#define CP_WAIT(n)  asm volatile("cp.async.wait_group %0;" :: "n"(n) : "memory")

static __device__ __forceinline__ void ldsm_x4(uint32_t& r0, uint32_t& r1, uint32_t& r2, uint32_t& r3,
                                               uint32_t addr) {
    asm volatile("ldmatrix.sync.aligned.m8n8.x4.shared.b16 {%0,%1,%2,%3}, [%4];"
                 : "=r"(r0), "=r"(r1), "=r"(r2), "=r"(r3) : "r"(addr));
}
static __device__ __forceinline__ void mma_bf16(float* c, const uint32_t* a, const uint32_t* b) {
    asm volatile(
        "mma.sync.aligned.m16n8k16.row.col.f32.bf16.bf16.f32 "
        "{%0,%1,%2,%3}, {%4,%5,%6,%7}, {%8,%9}, {%0,%1,%2,%3};"
        : "+f"(c[0]), "+f"(c[1]), "+f"(c[2]), "+f"(c[3])
        : "r"(a[0]), "r"(a[1]), "r"(a[2]), "r"(a[3]), "r"(b[0]), "r"(b[1]));
}
static __device__ __forceinline__ void split_bf16(float v, bf16& h, bf16& l) {
    h = __float2bfloat16(v);
    l = __float2bfloat16(v - __bfloat162float(h));
}

#define SMEM_PROJ (1024 + 2 * 4 * 16384)          // rbuf + 2 stages * 4 planes
#define SMEM_ATT  (1024 + 3 * 4 * 16384)          // rbuf + Q + K/P + V regions

// ---------------- projection GEMM (bf16x2 split, HMMA, fragment reuse) ----------------
// C[m][n] = sum_k A[m][k]*B[n][k]; 128x128 tile; MODE 0=Q(RMS), 1=K(RMS,+P), 2=V(transpose)
template <int MODE>
__global__ __launch_bounds__(256, 1) void proj_kernel(
    const bf16* __restrict__ Ah, const bf16* __restrict__ Al, int lda,
    const bf16* __restrict__ Bh, const bf16* __restrict__ Bl, int ldb, int kdim)
{
    extern __shared__ char smem[];
    float* rbuf = (float*)smem;
    const uint32_t sb = smem_u32(smem);
    const int tid = threadIdx.x;
    const int wid = tid >> 5, l = tid & 31;
    const int wm = wid >> 1, wn = wid & 1;
    const int bn = blockIdx.x * 128, bm = blockIdx.y * 128;

    float acc[2][8][4];
#pragma unroll
    for (int t = 0; t < 2; t++)
#pragma unroll
        for (int nb = 0; nb < 8; nb++)
#pragma unroll
            for (int i = 0; i < 4; i++) acc[t][nb][i] = 0.f;

    const int nch = kdim >> 6;

    auto load_chunk = [&](int c) {
        const int st = c & 1;
        const int k0 = c << 6;
#pragma unroll
        for (int p = 0; p < 4; p++) {
            const bf16* src = (p == 0) ? Ah : (p == 1) ? Al : (p == 2) ? Bh : Bl;
            const int ld = (p < 2) ? lda : ldb;
            const int r0 = (p < 2) ? bm : bn;
            const uint32_t dstb = sb + 1024 + st * 65536 + p * 16384;
#pragma unroll
            for (int i = tid; i < 1024; i += 256) {
                const int row = i >> 3, cc = i & 7;
                const uint32_t off = (uint32_t)(row * 128 + cc * 16);
                cp_async16(dstb + (off ^ (uint32_t)((row & 7) << 4)),
                           src + (size_t)(r0 + row) * ld + k0 + cc * 8);
            }
        }
        CP_COMMIT();
    };

    load_chunk(0);
    if (nch > 1) load_chunk(1);

    for (int c = 0; c < nch; c++) {
        if (c + 1 < nch) { CP_WAIT(1); } else { CP_WAIT(0); }
        __syncthreads();
        const uint32_t sbase = sb + 1024 + (c & 1) * 65536;

#pragma unroll
        for (int kk = 0; kk < 4; kk++) {
            uint32_t aH[2][4], aL[2][4];
#pragma unroll
            for (int t = 0; t < 2; t++) {
                const int mrow = wm * 32 + t * 16 + (l & 7) + ((l >> 3) & 1) * 8;
                const int kb = kk * 32 + ((l >> 4) & 1) * 16;
                const uint32_t ao = (uint32_t)(mrow * 128) + (uint32_t)(kb ^ ((mrow & 7) << 4));
                ldsm_x4(aH[t][0], aH[t][1], aH[t][2], aH[t][3], sbase + 0 * 16384 + ao);
                ldsm_x4(aL[t][0], aL[t][1], aL[t][2], aL[t][3], sbase + 1 * 16384 + ao);
            }
            uint32_t bH[8][2], bL[8][2];
#pragma unroll
            for (int bt = 0; bt < 4; bt++) {
                const int nrow = wn * 64 + bt * 16 + (l & 7) + ((l >> 4) & 1) * 8;
                const int kb = kk * 32 + ((l >> 3) & 1) * 16;
                const uint32_t bo = (uint32_t)(nrow * 128) + (uint32_t)(kb ^ ((nrow & 7) << 4));
                ldsm_x4(bH[2 * bt][0], bH[2 * bt][1], bH[2 * bt + 1][0], bH[2 * bt + 1][1],
                        sbase + 2 * 16384 + bo);
                ldsm_x4(bL[2 * bt][0], bL[2 * bt][1], bL[2 * bt + 1][0], bL[2 * bt + 1][1],
                        sbase + 3 * 16384 + bo);
            }
#pragma unroll
            for (int t = 0; t < 2; t++)
#pragma unroll
                for (int nb = 0; nb < 8; nb++) {
                    mma_bf16(acc[t][nb], aH[t], bH[nb]);
                    mma_bf16(acc[t][nb], aH[t], bL[nb]);
                    mma_bf16(acc[t][nb], aL[t], bH[nb]);
                }
        }
        __syncthreads();
        if (c + 2 < nch) load_chunk(c + 2);
    }

    // epilogues: acc[t][nb][i] -> row = wm*32+t*16+(l>>2)+(i>>1)*8, col = wn*64+nb*8+(l&3)*2+(i&1)
    if (MODE == 0 || MODE == 1) {
        float ss[4] = {0.f, 0.f, 0.f, 0.f};
#pragma unroll
        for (int t = 0; t < 2; t++)
#pragma unroll
            for (int nb = 0; nb < 8; nb++)
#pragma unroll
                for (int i = 0; i < 4; i++) {
                    const float v = acc[t][nb][i];
                    ss[t * 2 + (i >> 1)] += v * v;
                }
#pragma unroll
        for (int s = 0; s < 4; s++) {
            ss[s] += __shfl_xor_sync(0xffffffffu, ss[s], 1);
            ss[s] += __shfl_xor_sync(0xffffffffu, ss[s], 2);
        }
        if ((l & 3) == 0) {
#pragma unroll
            for (int s = 0; s < 4; s++) {
                const int row = wm * 32 + (s >> 1) * 16 + (l >> 2) + (s & 1) * 8;
                rbuf[wn * 128 + row] = ss[s];
            }
        }
        __syncthreads();

        bf16* dh = (MODE == 0) ? g_Qh : g_Kh;
        bf16* dl = (MODE == 0) ? g_Ql : g_Kl;
#pragma unroll
        for (int t = 0; t < 2; t++)
#pragma unroll
            for (int rh = 0; rh < 2; rh++) {
                const int row = wm * 32 + t * 16 + (l >> 2) + rh * 8;
                const float sc = rsqrtf((rbuf[row] + rbuf[128 + row]) * (1.0f / 128.0f));
                const size_t rowbase = (MODE == 0)
                    ? ((size_t)blockIdx.x * Mq + bm + row) * 128
                    : ((size_t)blockIdx.x * NKEYS + Pp + bm + row) * 128;
#pragma unroll
                for (int nb = 0; nb < 8; nb++) {
                    const int col = wn * 64 + nb * 8 + (l & 3) * 2;
                    const float v0 = acc[t][nb][rh * 2 + 0] * sc;
                    const float v1 = acc[t][nb][rh * 2 + 1] * sc;
                    bf16 h0, l0, h1, l1;
                    split_bf16(v0, h0, l0);
                    split_bf16(v1, h1, l1);
                    __nv_bfloat162 ph; ph.x = h0; ph.y = h1;
                    __nv_bfloat162 pl; pl.x = l0; pl.y = l1;
                    *(__nv_bfloat162*)(dh + rowbase + col) = ph;
                    *(__nv_bfloat162*)(dl + rowbase + col) = pl;
                }
            }
    } else { // MODE 2: V transposed store
        const int head = blockIdx.x;
#pragma unroll
        for (int t = 0; t < 2; t++)
#pragma unroll
            for (int nb = 0; nb < 8; nb++)
#pragma unroll
                for (int i = 0; i < 4; i++) {
                    const int row = wm * 32 + t * 16 + (l >> 2) + (i >> 1) * 8;
                    const int col = wn * 64 + nb * 8 + (l & 3) * 2 + (i & 1);
                    bf16 h, lo;
                    split_bf16(acc[t][nb][i], h, lo);
                    const size_t idx = ((size_t)head * Dd + col) * NKEYS + Pp + bm + row;
                    g_Vth[idx] = h;
                    g_Vtl[idx] = lo;
                }
    }
}

// ---------------- fused flash attention ----------------
// grid (Mq/128, Hh); per CTA: Q tile resident; loop 32 key tiles:
// S = Q K^T (split MMA), exp in regs, P split -> smem (K region), out += P V^T (split MMA).
__global__ __launch_bounds__(256, 1) void attn_kernel(float* __restrict__ outp)
{
    extern __shared__ char smem[];
    float* rbuf = (float*)smem;
    const uint32_t sb = smem_u32(smem);
    const uint32_t Qb = sb + 1024;
    const uint32_t Kb = Qb + 65536;
    const uint32_t Vb = Kb + 65536;
    char* Kc = smem + 1024 + 65536;   // byte pointer to K/P region

    const int tid = threadIdx.x;
    const int wid = tid >> 5, l = tid & 31;
    const int wm = wid >> 1, wn = wid & 1;
    const int bm = blockIdx.x * 128;
    const int z = blockIdx.y;

    const bf16* Qhp = g_Qh + ((size_t)z * Mq + bm) * Dd;
    const bf16* Qlp = g_Ql + ((size_t)z * Mq + bm) * Dd;
    const bf16* Khp = g_Kh + (size_t)z * NKEYS * Dd;
    const bf16* Klp = g_Kl + (size_t)z * NKEYS * Dd;
    const bf16* Vhp = g_Vth + (size_t)z * Dd * NKEYS;
    const bf16* Vlp = g_Vtl + (size_t)z * Dd * NKEYS;

    // plane layout in each 64KB region: p = split*2 + chunk (chunk = 64-elem half of k-dim)
    auto load_region = [&](uint32_t dstb, const bf16* srcH, const bf16* srcL,
                           int ld, int row0, int col0) {
#pragma unroll
        for (int p = 0; p < 4; p++) {
            const bf16* src = (p < 2) ? srcH : srcL;
            const int k0 = col0 + (p & 1) * 64;
#pragma unroll
            for (int i = tid; i < 1024; i += 256) {
                const int row = i >> 3, cc = i & 7;
                const uint32_t off = (uint32_t)(row * 128 + cc * 16);
                cp_async16(dstb + p * 16384 + (off ^ (uint32_t)((row & 7) << 4)),
                           src + (size_t)(row0 + row) * ld + k0 + cc * 8);
            }
        }
    };

    // split-MMA over one 128-deep k dim: A region planes [abase], B region [bbase]
    auto do_mma = [&](uint32_t abase, uint32_t bbase, float acc[2][8][4]) {
#pragma unroll
        for (int c = 0; c < 2; c++) {
            const uint32_t aHb = abase + c * 16384, aLb = abase + (2 + c) * 16384;
            const uint32_t bHb = bbase + c * 16384, bLb = bbase + (2 + c) * 16384;
#pragma unroll
            for (int kk = 0; kk < 4; kk++) {
                uint32_t aH[2][4], aL[2][4];
#pragma unroll
                for (int t = 0; t < 2; t++) {
                    const int mrow = wm * 32 + t * 16 + (l & 7) + ((l >> 3) & 1) * 8;
                    const int kb = kk * 32 + ((l >> 4) & 1) * 16;
                    const uint32_t ao = (uint32_t)(mrow * 128) + (uint32_t)(kb ^ ((mrow & 7) << 4));
                    ldsm_x4(aH[t][0], aH[t][1], aH[t][2], aH[t][3], aHb + ao);
                    ldsm_x4(aL[t][0], aL[t][1], aL[t][2], aL[t][3], aLb + ao);
                }
                uint32_t bH[8][2], bL[8][2];
#pragma unroll
                for (int bt = 0; bt < 4; bt++) {
                    const int nrow = wn * 64 + bt * 16 + (l & 7) + ((l >> 4) & 1) * 8;
                    const int kb = kk * 32 + ((l >> 3) & 1) * 16;
                    const uint32_t bo = (uint32_t)(nrow * 128) + (uint32_t)(kb ^ ((nrow & 7) << 4));
                    ldsm_x4(bH[2 * bt][0], bH[2 * bt][1], bH[2 * bt + 1][0], bH[2 * bt + 1][1], bHb + bo);
                    ldsm_x4(bL[2 * bt][0], bL[2 * bt][1], bL[2 * bt + 1][0], bL[2 * bt + 1][1], bLb + bo);
                }
#pragma unroll
                for (int t = 0; t < 2; t++)
#pragma unroll
                    for (int nb = 0; nb < 8; nb++) {
                        mma_bf16(acc[t][nb], aH[t], bH[nb]);
                        mma_bf16(acc[t][nb], aH[t], bL[nb]);
                        mma_bf16(acc[t][nb], aL[t], bH[nb]);
                    }
            }
        }
    };

    float accO[2][8][4];
#pragma unroll
    for (int t = 0; t < 2; t++)
#pragma unroll
        for (int nb = 0; nb < 8; nb++)
#pragma unroll
            for (int i = 0; i < 4; i++) accO[t][nb][i] = 0.f;
    float rs[4] = {0.f, 0.f, 0.f, 0.f};

    // prologue: Q tile + K tile 0 in one group
    load_region(Qb, Qhp, Qlp, Dd, 0, 0);
    load_region(Kb, Khp, Klp, Dd, 0, 0);
    CP_COMMIT();

    for (int it = 0; it < NKEYS / 128; it++) {
        const int bn = it * 128;
        // issue V_it (V buffer free since end of previous iter)
        load_region(Vb, Vhp, Vlp, NKEYS, 0, bn);
        CP_COMMIT();

        CP_WAIT(1);            // K_it (and Q on first iter) complete
        __syncthreads();

        float accS[2][8][4];
#pragma unroll
        for (int t = 0; t < 2; t++)
#pragma unroll
            for (int nb = 0; nb < 8; nb++)
#pragma unroll
                for (int i = 0; i < 4; i++) accS[t][nb][i] = 0.f;

        do_mma(Qb, Kb, accS);   // S = Q K^T
        __syncthreads();        // all warps done reading K region

        // exp + split + store P into K region; accumulate row sums
#pragma unroll
        for (int t = 0; t < 2; t++)
#pragma unroll
            for (int rh = 0; rh < 2; rh++) {
                const int row = wm * 32 + t * 16 + (l >> 2) + rh * 8;
#pragma unroll
                for (int nb = 0; nb < 8; nb++) {
                    const int col = wn * 64 + nb * 8 + (l & 3) * 2;
                    const float e0 = __expf(accS[t][nb][rh * 2 + 0]);
                    const float e1 = __expf(accS[t][nb][rh * 2 + 1]);
                    rs[t * 2 + rh] += e0 + e1;
                    bf16 h0, l0, h1, l1;
                    split_bf16(e0, h0, l0);
                    split_bf16(e1, h1, l1);
                    const uint32_t off = (uint32_t)(row * 128 + (col & 63) * 2);
                    const uint32_t sw = off ^ (uint32_t)((row & 7) << 4);
                    uint32_t ph, pl;
                    {
                        __nv_bfloat162 tmp; tmp.x = h0; tmp.y = h1;
                        ph = *(uint32_t*)&tmp;
                        tmp.x = l0; tmp.y = l1;
                        pl = *(uint32_t*)&tmp;
                    }
                    *(uint32_t*)(Kc + (0 * 2 + wn) * 16384 + sw) = ph;
                    *(uint32_t*)(Kc + (1 * 2 + wn) * 16384 + sw) = pl;
                }
            }
        CP_WAIT(0);             // V_it complete
        __syncthreads();        // P visible to all; V visible to all

        do_mma(Kb, Vb, accO);   // out += P V^T
        __syncthreads();        // all warps done reading P/V

        if (it + 1 < NKEYS / 128) {
            load_region(Kb, Khp, Klp, Dd, bn + 128, 0);   // K_{it+1} into K/P region
            CP_COMMIT();
        }
    }

    // final: reduce row sums across quads and the two n-warps; scale + store
#pragma unroll
    for (int s = 0; s < 4; s++) {
        rs[s] += __shfl_xor_sync(0xffffffffu, rs[s], 1);
        rs[s] += __shfl_xor_sync(0xffffffffu, rs[s], 2);
    }
    if ((l & 3) == 0) {
#pragma unroll
        for (int s = 0; s < 4; s++) {
            const int row = wm * 32 + (s >> 1) * 16 + (l >> 2) + (s & 1) * 8;
            rbuf[wn * 128 + row] = rs[s];
        }
    }
    __syncthreads();

#pragma unroll
    for (int t = 0; t < 2; t++)
#pragma unroll
        for (int rh = 0; rh < 2; rh++) {
            const int row = wm * 32 + t * 16 + (l >> 2) + rh * 8;
            const float inv = 1.0f / (rbuf[row] + rbuf[128 + row]);
            float* orow = outp + (size_t)(bm + row) * Nn + (size_t)z * Dd;
#pragma unroll
            for (int nb = 0; nb < 8; nb++) {
                const int col = wn * 64 + nb * 8 + (l & 3) * 2;
                float2 v;
                v.x = accO[t][nb][rh * 2 + 0] * inv;
                v.y = accO[t][nb][rh * 2 + 1] * inv;
                *(float2*)(orow + col) = v;
            }
        }
}

// ---------------- prep kernels ----------------
__global__ __launch_bounds__(256) void convert_X(const float* __restrict__ X) {
    const size_t n = (size_t)Mq * Nn;
    for (size_t i = (size_t)blockIdx.x * blockDim.x + threadIdx.x; i < n;
         i += (size_t)gridDim.x * blockDim.x) {
        bf16 h, lo;
        split_bf16(X[i], h, lo);
        g_Xh[i] = h;
        g_Xl[i] = lo;
    }
}

__global__ __launch_bounds__(256) void transpose_convert_W(
    const float* __restrict__ W, bf16* __restrict__ oh, bf16* __restrict__ ol)
{
    __shared__ float t[32][33];
    const int n0 = blockIdx.x * 32, k0 = blockIdx.y * 32;
    const int tx = threadIdx.x, ty = threadIdx.y;
#pragma unroll
    for (int j = 0; j < 4; j++)
        t[ty + 8 * j][tx] = W[(size_t)(k0 + ty + 8 * j) * Nn + n0 + tx];
    __syncthreads();
#pragma unroll
    for (int j = 0; j < 4; j++) {
        const float v = t[tx][ty + 8 * j];
        const size_t o = (size_t)(n0 + ty + 8 * j) * Nn + k0 + tx;
        bf16 h, lo;
        split_bf16(v, h, lo);
        oh[o] = h;
        ol[o] = lo;
    }
}

__global__ __launch_bounds__(256) void convert_cacheK(const float* __restrict__ cK) {
    const size_t n = (size_t)Hh * Pp * Dd;
    for (size_t i = (size_t)blockIdx.x * blockDim.x + threadIdx.x; i < n;
         i += (size_t)gridDim.x * blockDim.x) {
        const size_t h = i / ((size_t)Pp * Dd);
        const size_t rr = i % ((size_t)Pp * Dd);
        bf16 hh, lo;
        split_bf16(cK[i], hh, lo);
        const size_t o = h * (size_t)NKEYS * Dd + rr;
        g_Kh[o] = hh;
        g_Kl[o] = lo;
    }
}

__global__ __launch_bounds__(256) void transpose_convert_V(const float* __restrict__ cV) {
    __shared__ float t[32][33];
    const int h = blockIdx.z;
    const int p0 = blockIdx.x * 32, d0 = blockIdx.y * 32;
    const int tx = threadIdx.x, ty = threadIdx.y;
#pragma unroll
    for (int j = 0; j < 4; j++)
        t[ty + 8 * j][tx] = cV[((size_t)h * Pp + p0 + ty + 8 * j) * Dd + d0 + tx];
    __syncthreads();
#pragma unroll
    for (int j = 0; j < 4; j++) {
        const float v = t[tx][ty + 8 * j];
        const size_t o = ((size_t)h * Dd + d0 + ty + 8 * j) * NKEYS + p0 + tx;
        bf16 hh, lo;
        split_bf16(v, hh, lo);
        g_Vth[o] = hh;
        g_Vtl[o] = lo;
    }
}

// ---------------- host launcher ----------------
extern "C" void kernel_launch(void* const* d_in, const int* in_sizes, int n_in,
                              void* d_out, int out_size)
{
    const float* X  = (const float*)d_in[0];
    const float* Wq = (const float*)d_in[1];
    const float* Wk = (const float*)d_in[2];
    const float* Wv = (const float*)d_in[3];
    const float* cK = (const float*)d_in[4];
    const float* cV = (const float*)d_in[5];
    float* out = (float*)d_out;

    bf16 *xh, *xl, *wh, *wl;
    cudaGetSymbolAddress((void**)&xh, g_Xh);   cudaGetSymbolAddress((void**)&xl, g_Xl);
    cudaGetSymbolAddress((void**)&wh, g_Wh);   cudaGetSymbolAddress((void**)&wl, g_Wl);

    cudaFuncSetAttribute(proj_kernel<0>, cudaFuncAttributeMaxDynamicSharedMemorySize, SMEM_PROJ);
    cudaFuncSetAttribute(proj_kernel<1>, cudaFuncAttributeMaxDynamicSharedMemorySize, SMEM_PROJ);
    cudaFuncSetAttribute(proj_kernel<2>, cudaFuncAttributeMaxDynamicSharedMemorySize, SMEM_PROJ);
    cudaFuncSetAttribute(attn_kernel,    cudaFuncAttributeMaxDynamicSharedMemorySize, SMEM_ATT);

    // prep
    convert_X<<<2048, 256>>>(X);
    transpose_convert_W<<<dim3(128, 128), dim3(32, 8)>>>(Wq, wh + (size_t)0 * Nn * Nn, wl + (size_t)0 * Nn * Nn);
    transpose_convert_W<<<dim3(128, 128), dim3(32, 8)>>>(Wk, wh + (size_t)1 * Nn * Nn, wl + (size_t)1 * Nn * Nn);
    transpose_convert_W<<<dim3(128, 128), dim3(32, 8)>>>(Wv, wh + (size_t)2 * Nn * Nn, wl + (size_t)2 * Nn * Nn);
    convert_cacheK<<<8192, 256>>>(cK);
    transpose_convert_V<<<dim3(Pp / 32, Dd / 32, Hh), dim3(32, 8)>>>(cV);

    // projections
    {
        dim3 grid(Nn / 128, Mq / 128, 1);
        proj_kernel<0><<<grid, 256, SMEM_PROJ>>>(xh, xl, Nn,
            wh + (size_t)0 * Nn * Nn, wl + (size_t)0 * Nn * Nn, Nn, Nn);
        proj_kernel<1><<<grid, 256, SMEM_PROJ>>>(xh, xl, Nn,
            wh + (size_t)1 * Nn * Nn, wl + (size_t)1 * Nn * Nn, Nn, Nn);
        proj_kernel<2><<<grid, 256, SMEM_PROJ>>>(xh, xl, Nn,
            wh + (size_t)2 * Nn * Nn, wl + (size_t)2 * Nn * Nn, Nn, Nn);
    }

    // fused attention
    attn_kernel<<<dim3(Mq / 128, Hh), 256, SMEM_ATT>>>(out);
}